// round 10
// baseline (speedup 1.0000x reference)
#include <cuda_runtime.h>
#include <cuda_bf16.h>
#include <string.h>
#include <math.h>

// ---------------- problem constants ----------------
#define EID   30000
#define EMB   256
#define HID   512
#define SRC_T 128
#define TRG_T 50
#define B     64
#define G3    1536
#define NB    296            // persistent blocks = 148 SMs x 2
#define LTILES 469           // logits tiles of 64 cols (469*64 = 30016)

// ---------------- device state ----------------
__device__ float g_hT[2 * HID * B];                   // transposed hidden [k][b], double buffered
__device__ float g_giEnc[(size_t)SRC_T * B * G3];     // encoder gi (incl b_ih)
__device__ float g_A[8 * B * G3];                     // gh partials
__device__ float g_Bp[5 * B * G3];                    // gi partials (decoder)
__device__ float g_C[12 * B * HID];                   // r1 partials
__device__ float g_logits[(size_t)B * EID];
__device__ float g_rate[B];
__device__ int   g_idx[B];
__device__ float g_pm[B * 5], g_ps[B * 5];
__device__ int   g_pi[B * 5];
__device__ unsigned g_leaf[8 * 32];                   // 8 leaf counters, 128B apart
__device__ unsigned g_root, g_gen, g_ticket;

// ---------------- packed fp32 FMA ----------------
__device__ __forceinline__ float2 ffma2(float2 a, float2 b, float2 c) {
    unsigned long long ua, ub, uc, ud;
    memcpy(&ua, &a, 8); memcpy(&ub, &b, 8); memcpy(&uc, &c, 8);
    asm("fma.rn.f32x2 %0, %1, %2, %3;" : "=l"(ud) : "l"(ua), "l"(ub), "l"(uc));
    float2 d; memcpy(&d, &ud, 8); return d;
}

__device__ __forceinline__ float sigf(float x) { return 1.f / (1.f + expf(-x)); }

// ---------------- hierarchical grid barrier (monotonic, no resets) ----------------
// 296 blocks: leaf = bx & 7 -> exactly 37 arrivals per leaf per barrier.
__device__ __forceinline__ void gbar(unsigned& nb) {
    nb++;
    __syncthreads();
    if (threadIdx.x == 0) {
        __threadfence();
        unsigned leaf = blockIdx.x & 7;
        if (atomicAdd(&g_leaf[leaf * 32], 1u) == nb * 37u - 1u) {
            if (atomicAdd(&g_root, 1u) == nb * 8u - 1u) {
                __threadfence();
                *(volatile unsigned*)&g_gen = nb;
            }
        }
        while (*(volatile unsigned*)&g_gen < nb) { __nanosleep(96); }
        __threadfence();
    }
    __syncthreads();
}

// ---------------- 64x64 micro-kernel (4 pairs x 4 cols / thread, 128 thr) ----------------
__device__ __forceinline__ void mm64_4x4(const float* __restrict__ xs,
                                         const float* __restrict__ ws,
                                         int bpg, int cg, float2 acc[4][4]) {
    #pragma unroll 4
    for (int k = 0; k < 64; k++) {
        float2 xv[4];
        #pragma unroll
        for (int i = 0; i < 4; i++)
            xv[i] = *reinterpret_cast<const float2*>(&xs[k * 66 + 2 * (bpg + 8 * i)]);
        #pragma unroll
        for (int c = 0; c < 4; c++) {
            float w = ws[(cg * 4 + c) * 65 + k];
            float2 wp = make_float2(w, w);
            #pragma unroll
            for (int i = 0; i < 4; i++) acc[i][c] = ffma2(xv[i], wp, acc[i][c]);
        }
    }
}

__device__ __forceinline__ void store_4x4(float* __restrict__ dst, int N, int n0,
                                          int bpg, int cg, float2 acc[4][4]) {
    #pragma unroll
    for (int c = 0; c < 4; c++) {
        int n = n0 + cg * 4 + c;
        #pragma unroll
        for (int i = 0; i < 4; i++) {
            int p = bpg + 8 * i;
            dst[(size_t)(2 * p) * N + n]     = acc[i][c].x;
            dst[(size_t)(2 * p + 1) * N + n] = acc[i][c].y;
        }
    }
}

// merge the 5 per-slice softmax partials of batch b -> (lse, first-argmax)
__device__ __forceinline__ void merge5(int b, float& lse, int& amax) {
    float M = -3.4e38f, S = 0.f; int I = 0x7fffffff;
    #pragma unroll
    for (int sl = 0; sl < 5; sl++) {
        float m2 = g_pm[b * 5 + sl], s2 = g_ps[b * 5 + sl];
        int i2 = g_pi[b * 5 + sl];
        float Mn = fmaxf(M, m2);
        S = S * expf(M - Mn) + s2 * expf(m2 - Mn);
        I = (m2 > M) ? i2 : ((M > m2) ? I : min(I, i2));
        M = Mn;
    }
    lse = M + logf(S);
    amax = I;
}

// ---------------- prep kernels ----------------
__global__ void init_state(const int* __restrict__ trg_eid, const float* __restrict__ trg_rate) {
    int i = blockIdx.x * 256 + threadIdx.x;
    if (i < HID * B) g_hT[i] = 0.f;
    if (i < B) { g_idx[i] = trg_eid[i]; g_rate[i] = trg_rate[i]; }
    if (i < 8 * 32) g_leaf[i] = 0u;
    if (i == 0) { g_root = 0u; g_gen = 0u; g_ticket = 0u; }
}

__global__ void enc_gi(const float* __restrict__ src, const float* __restrict__ W_ih,
                       const float* __restrict__ b_ih) {
    int j = blockIdx.x * 256 + threadIdx.x;
    int tb = blockIdx.y;
    if (j < G3) {
        const float* x = src + (size_t)tb * 3;
        g_giEnc[(size_t)tb * G3 + j] = b_ih[j] + x[0] * W_ih[j * 3] + x[1] * W_ih[j * 3 + 1]
                                               + x[2] * W_ih[j * 3 + 2];
    }
}

// ---------------- the persistent kernel: encoder + decoder ----------------
__global__ __launch_bounds__(128, 2)
void mono_kernel(const int* __restrict__ src_len,
                 const float* __restrict__ W_hh_enc, const float* __restrict__ b_hh_enc,
                 const float* __restrict__ emb_dec,
                 const float* __restrict__ W_ih_dec, const float* __restrict__ W_hh_dec,
                 const float* __restrict__ b_ih_dec, const float* __restrict__ b_hh_dec,
                 const float* __restrict__ emb_mt,
                 const float* __restrict__ W_eid, const float* __restrict__ b_eid,
                 const float* __restrict__ W_r1, const float* __restrict__ b_r1,
                 const float* __restrict__ W_r2, const float* __restrict__ b_r2,
                 float* __restrict__ out)
{
    __shared__ __align__(16) float xs[64 * 66];
    __shared__ __align__(16) float ws[64 * 65];
    __shared__ unsigned sh_t;
    __shared__ int sh_amax[64];
    const int bx = blockIdx.x, tid = threadIdx.x;
    const int bpg = tid & 7, cg = tid >> 3;
    unsigned nb = 0;
    float* hb[2] = { g_hT, g_hT + HID * B };
    float* out_rate = out + (size_t)TRG_T * B * EID;

    // ================= encoder: 128 masked GRU steps =================
    for (int t = 0; t < SRC_T; t++) {
        const float* h = hb[t & 1];
        float* hn = hb[(t + 1) & 1];

        if (bx < 192) {   // gh GEMM: 24 n-tiles x 8 k-chunks
            int jn = bx % 24, jk = bx / 24;
            int n0 = jn * 64, k0 = jk * 64;
            for (int e = tid; e < 4096; e += 128) {
                int k = e >> 6, b = e & 63;
                xs[k * 66 + b] = h[(k0 + k) * 64 + b];
            }
            for (int e = tid; e < 4096; e += 128) {
                int nl = e >> 6, k = e & 63;
                ws[nl * 65 + k] = W_hh_enc[(size_t)(n0 + nl) * HID + k0 + k];
            }
            __syncthreads();
            float2 acc[4][4];
            #pragma unroll
            for (int i = 0; i < 4; i++)
                #pragma unroll
                for (int c = 0; c < 4; c++) acc[i][c] = make_float2(0.f, 0.f);
            mm64_4x4(xs, ws, bpg, cg, acc);
            store_4x4(g_A + (size_t)jk * B * G3, G3, n0, bpg, cg, acc);
            __syncthreads();
        }
        gbar(nb);

        {   // combine: 1 (b,j) per thread
            int i = bx * 128 + tid;
            if (i < B * HID) {
                int b = i >> 9, j = i & 511;
                float ar = b_hh_enc[j], az = b_hh_enc[j + 512], an = b_hh_enc[j + 1024];
                #pragma unroll
                for (int p = 0; p < 8; p++) {
                    const float* ba = g_A + ((size_t)p * B + b) * G3;
                    ar += ba[j]; az += ba[j + 512]; an += ba[j + 1024];
                }
                const float* gi = g_giEnc + ((size_t)t * B + b) * G3;
                float r = sigf(ar + gi[j]);
                float z = sigf(az + gi[j + 512]);
                float n = tanhf(gi[j + 1024] + r * an);
                float ho = h[j * 64 + b];
                hn[j * 64 + b] = (t < src_len[b]) ? (1.f - z) * n + z * ho : ho;
            }
        }
        gbar(nb);
    }

    // ================= decoder: 49 autoregressive steps =================
    for (int s = 0; s < TRG_T - 1; s++) {
        const float* hcur = hb[s & 1];
        float* hnew = hb[(s + 1) & 1];

        // ---- P1: gi+gh GEMM with fused input gather (312 jobs) ----
        for (int job = bx; job < 312; job += NB) {
            __syncthreads();
            int jn = job % 24, jk = job / 24;
            int n0 = jn * 64;
            if (jk < 5) {           // input part: emb_dec[idx] ++ rate, K chunk jk*64
                int kb = jk * 64;
                for (int e = tid; e < 4096; e += 128) {
                    int b = e >> 6, kl = e & 63, kk = kb + kl;
                    float v = 0.f;
                    if (kk < EMB)       v = emb_dec[(size_t)g_idx[b] * EMB + kk];
                    else if (kk == EMB) v = g_rate[b];
                    xs[kl * 66 + b] = v;
                }
                for (int e = tid; e < 4096; e += 128) {
                    int nl = e >> 6, k = e & 63, kk = kb + k;
                    ws[nl * 65 + k] = (kk < EMB + 1) ? W_ih_dec[(size_t)(n0 + nl) * (EMB + 1) + kk] : 0.f;
                }
            } else {                // hidden part
                int kb = (jk - 5) * 64;
                for (int e = tid; e < 4096; e += 128) {
                    int k = e >> 6, b = e & 63;
                    xs[k * 66 + b] = hcur[(kb + k) * 64 + b];
                }
                for (int e = tid; e < 4096; e += 128) {
                    int nl = e >> 6, k = e & 63;
                    ws[nl * 65 + k] = W_hh_dec[(size_t)(n0 + nl) * HID + kb + k];
                }
            }
            __syncthreads();
            float2 acc[4][4];
            #pragma unroll
            for (int i = 0; i < 4; i++)
                #pragma unroll
                for (int c = 0; c < 4; c++) acc[i][c] = make_float2(0.f, 0.f);
            mm64_4x4(xs, ws, bpg, cg, acc);
            float* dst = (jk < 5) ? (g_Bp + (size_t)jk * B * G3) : (g_A + (size_t)(jk - 5) * B * G3);
            store_4x4(dst, G3, n0, bpg, cg, acc);
        }
        gbar(nb);

        // ---- P2: GRU combine + ticket reset ----
        if (bx == 0 && tid == 0) g_ticket = (unsigned)NB;   // static-first tiles are 0..NB-1
        {
            int i = bx * 128 + tid;
            if (i < B * HID) {
                int b = i >> 9, j = i & 511;
                float ar = b_hh_dec[j], az = b_hh_dec[j + 512], an = b_hh_dec[j + 1024];
                #pragma unroll
                for (int p = 0; p < 8; p++) {
                    const float* ba = g_A + ((size_t)p * B + b) * G3;
                    ar += ba[j]; az += ba[j + 512]; an += ba[j + 1024];
                }
                float br = b_ih_dec[j], bz = b_ih_dec[j + 512], bn = b_ih_dec[j + 1024];
                #pragma unroll
                for (int p = 0; p < 5; p++) {
                    const float* bb = g_Bp + ((size_t)p * B + b) * G3;
                    br += bb[j]; bz += bb[j + 512]; bn += bb[j + 1024];
                }
                float r = sigf(ar + br);
                float z = sigf(az + bz);
                float n = tanhf(bn + r * an);
                float ho = hcur[j * 64 + b];
                hnew[j * 64 + b] = (1.f - z) * n + z * ho;
            }
        }
        gbar(nb);

        // ---- P3: logits GEMM, ticket-scheduled 64-col tiles ----
        {
            unsigned t = (unsigned)bx;        // static first tile
            while (t < LTILES) {
                int n0 = (int)t * 64;
                float2 acc[4][4];
                #pragma unroll
                for (int i = 0; i < 4; i++)
                    #pragma unroll
                    for (int c = 0; c < 4; c++) acc[i][c] = make_float2(0.f, 0.f);
                for (int kt = 0; kt < HID; kt += 64) {
                    __syncthreads();
                    for (int e = tid; e < 4096; e += 128) {
                        int k = e >> 6, b = e & 63;
                        xs[k * 66 + b] = hnew[(kt + k) * 64 + b];
                    }
                    for (int e = tid; e < 4096; e += 128) {
                        int nl = e >> 6, k = e & 63; int n = n0 + nl;
                        ws[nl * 65 + k] = (n < EID) ? W_eid[(size_t)n * HID + kt + k] : 0.f;
                    }
                    __syncthreads();
                    mm64_4x4(xs, ws, bpg, cg, acc);
                }
                #pragma unroll
                for (int c = 0; c < 4; c++) {
                    int n = n0 + cg * 4 + c;
                    if (n >= EID) continue;
                    float bv = b_eid[n];
                    #pragma unroll
                    for (int i = 0; i < 4; i++) {
                        int p = bpg + 8 * i;
                        g_logits[(size_t)(2 * p) * EID + n]     = acc[i][c].x + bv;
                        g_logits[(size_t)(2 * p + 1) * EID + n] = acc[i][c].y + bv;
                    }
                }
                __syncthreads();
                if (tid == 0) sh_t = atomicAdd(&g_ticket, 1u);
                __syncthreads();
                t = sh_t;
            }
        }
        gbar(nb);

        // ---- P4: online-softmax partials (64 b x 5 slices of 6000) ----
        for (int job = bx; job < 320; job += NB) {
            __syncthreads();
            int b = job % 64, sl = job / 64;
            const float* L = g_logits + (size_t)b * EID;
            int nb0 = sl * 6000;
            float m = -3.4e38f, sum = 0.f; int ix = 0x7fffffff;
            for (int n = nb0 + tid; n < nb0 + 6000; n += 128) {
                float v = L[n];
                if (v > m) { sum = sum * expf(m - v) + 1.f; m = v; ix = n; }
                else       sum += expf(v - m);
            }
            float* rm = xs; float* rs = xs + 128; int* ri = (int*)(xs + 256);
            rm[tid] = m; rs[tid] = sum; ri[tid] = ix;
            __syncthreads();
            for (int st = 64; st; st >>= 1) {
                if (tid < st) {
                    float m1 = rm[tid], m2 = rm[tid + st];
                    float s1 = rs[tid], s2 = rs[tid + st];
                    int i1 = ri[tid], i2 = ri[tid + st];
                    float M = fmaxf(m1, m2);
                    rs[tid] = s1 * expf(m1 - M) + s2 * expf(m2 - M);
                    rm[tid] = M;
                    ri[tid] = (m2 > m1) ? i2 : ((m1 > m2) ? i1 : min(i1, i2));
                }
                __syncthreads();
            }
            if (tid == 0) {
                g_pm[b * 5 + sl] = rm[0]; g_ps[b * 5 + sl] = rs[0]; g_pi[b * 5 + sl] = ri[0];
            }
        }
        gbar(nb);

        // ---- P5: normalized write (320 jobs) + r1 GEMM (96 jobs), lse/amax merged locally ----
        for (int job = bx; job < 416; job += NB) {
            __syncthreads();
            if (job < 320) {
                int b = job % 64, sl = job / 64;
                float lse; int amax; merge5(b, lse, amax);
                const float* L = g_logits + (size_t)b * EID;
                float* O = out + ((size_t)(s + 1) * B + b) * EID;
                for (int n = sl * 6000 + tid; n < sl * 6000 + 6000; n += 128) O[n] = L[n] - lse;
                if (sl == 0 && tid == 0) g_idx[b] = amax;
            } else {
                int j = job - 320;
                int jn = j & 7, jk = j >> 3;
                int n0 = jn * 64, k0 = jk * 64;
                if (tid < 64) { float d; int a; merge5(tid, d, a); sh_amax[tid] = a; }
                __syncthreads();
                if (jk < 4) {   // emb_mt[argmax] region
                    for (int e = tid; e < 4096; e += 128) {
                        int b = e >> 6, kl = e & 63;
                        xs[kl * 66 + b] = emb_mt[(size_t)sh_amax[b] * EMB + k0 + kl];
                    }
                } else {        // h region
                    for (int e = tid; e < 4096; e += 128) {
                        int k = e >> 6, b = e & 63;
                        xs[k * 66 + b] = hnew[(k0 - EMB + k) * 64 + b];
                    }
                }
                for (int e = tid; e < 4096; e += 128) {
                    int nl = e >> 6, k = e & 63;
                    ws[nl * 65 + k] = W_r1[(size_t)(n0 + nl) * (EMB + HID) + k0 + k];
                }
                __syncthreads();
                float2 acc[4][4];
                #pragma unroll
                for (int i = 0; i < 4; i++)
                    #pragma unroll
                    for (int c = 0; c < 4; c++) acc[i][c] = make_float2(0.f, 0.f);
                mm64_4x4(xs, ws, bpg, cg, acc);
                store_4x4(g_C + (size_t)jk * B * HID, HID, n0, bpg, cg, acc);
            }
        }
        gbar(nb);

        // ---- P6: rate head (blocks 0..63) ----
        if (bx < 64) {
            int b = bx;
            float a = 0.f;
            #pragma unroll
            for (int q = 0; q < 4; q++) {
                int j = tid + 128 * q;
                float v = b_r1[j];
                #pragma unroll
                for (int p = 0; p < 12; p++) v += g_C[((size_t)p * B + b) * HID + j];
                a += fmaxf(v, 0.f) * W_r2[j];
            }
            float* rs = xs;
            __syncthreads();
            rs[tid] = a; __syncthreads();
            for (int st = 64; st; st >>= 1) { if (tid < st) rs[tid] += rs[tid + st]; __syncthreads(); }
            if (tid == 0) {
                float pr = sigf(rs[0] + b_r2[0]);
                out_rate[(size_t)(s + 1) * B + b] = pr;
                g_rate[b] = pr;
            }
        }
        gbar(nb);
    }
}

// ---------------- host launcher ----------------
extern "C" void kernel_launch(void* const* d_in, const int* in_sizes, int n_in,
                              void* d_out, int out_size)
{
    const float* src      = (const float*)d_in[0];
    const int*   src_len  = (const int*)  d_in[1];
    const int*   trg_eid  = (const int*)  d_in[2];
    const float* trg_rate = (const float*)d_in[3];
    const float* W_ih_enc = (const float*)d_in[4];
    const float* W_hh_enc = (const float*)d_in[5];
    const float* b_ih_enc = (const float*)d_in[6];
    const float* b_hh_enc = (const float*)d_in[7];
    const float* emb_dec  = (const float*)d_in[8];
    const float* W_ih_dec = (const float*)d_in[9];
    const float* W_hh_dec = (const float*)d_in[10];
    const float* b_ih_dec = (const float*)d_in[11];
    const float* b_hh_dec = (const float*)d_in[12];
    const float* emb_mt   = (const float*)d_in[13];
    const float* W_eid    = (const float*)d_in[14];
    const float* b_eid    = (const float*)d_in[15];
    const float* W_r1     = (const float*)d_in[16];
    const float* b_r1     = (const float*)d_in[17];
    const float* W_r2     = (const float*)d_in[18];
    const float* b_r2     = (const float*)d_in[19];
    float* out = (float*)d_out;
    float* out_rate = out + (size_t)TRG_T * B * EID;

    // zero output row 0 (eid + rate)
    cudaMemsetAsync(out, 0, (size_t)B * EID * sizeof(float), 0);
    cudaMemsetAsync(out_rate, 0, B * sizeof(float), 0);

    init_state<<<128, 256>>>(trg_eid, trg_rate);
    enc_gi<<<dim3(6, SRC_T * B), 256>>>(src, W_ih_enc, b_ih_enc);

    mono_kernel<<<NB, 128>>>(src_len, W_hh_enc, b_hh_enc,
                             emb_dec, W_ih_dec, W_hh_dec, b_ih_dec, b_hh_dec,
                             emb_mt, W_eid, b_eid, W_r1, b_r1, W_r2, b_r2, out);
}

// round 11
// speedup vs baseline: 1.8728x; 1.8728x over previous
#include <cuda_runtime.h>
#include <cuda_bf16.h>
#include <string.h>
#include <math.h>

// ---------------- problem constants ----------------
#define EID   30000
#define EMB   256
#define HID   512
#define SRC_T 128
#define TRG_T 50
#define B     64
#define G3    (3*HID)          // 1536

// ---------------- device state ----------------
__device__ float g_hT[2 * HID * B];                    // hidden, transposed [j][b], double buffered
__device__ float g_giEnc[(size_t)SRC_T * G3 * B];      // encoder gi, [t][j][b] (incl. b_ih)
__device__ float g_A[8 * G3 * B];                      // gh partials, [p][j][b]
__device__ float g_Bp[5 * G3 * B];                     // gi partials (decoder), [p][j][b]
__device__ float g_C[12 * B * HID];                    // r1 partials, [p][b][j]
__device__ float g_logits[(size_t)B * EID];
__device__ float g_pm[B * 5], g_ps[B * 5];
__device__ int   g_pi[B * 5];
__device__ float g_rate[B];
__device__ int   g_idx[B];

// ---------------- packed fp32 FMA (sm_100+) ----------------
__device__ __forceinline__ float2 ffma2(float2 a, float2 b, float2 c) {
    unsigned long long ua, ub, uc, ud;
    memcpy(&ua, &a, 8); memcpy(&ub, &b, 8); memcpy(&uc, &c, 8);
    asm("fma.rn.f32x2 %0, %1, %2, %3;" : "=l"(ud) : "l"(ua), "l"(ub), "l"(uc));
    float2 d; memcpy(&d, &ud, 8); return d;
}

__device__ __forceinline__ float sigf(float x) { return 1.f / (1.f + expf(-x)); }

// ---------------- 64x64 micro-kernel (4 pairs x 4 cols / thread, 128 thr) ----------------
__device__ __forceinline__ void mm64_4x4(const float* __restrict__ xs,
                                         const float* __restrict__ ws,
                                         int bpg, int cg, float2 acc[4][4]) {
    #pragma unroll 4
    for (int k = 0; k < 64; k++) {
        float2 xv[4];
        #pragma unroll
        for (int i = 0; i < 4; i++)
            xv[i] = *reinterpret_cast<const float2*>(&xs[k * 66 + 2 * (bpg + 8 * i)]);
        #pragma unroll
        for (int c = 0; c < 4; c++) {
            float w = ws[(cg * 4 + c) * 65 + k];
            float2 wp = make_float2(w, w);
            #pragma unroll
            for (int i = 0; i < 4; i++) acc[i][c] = ffma2(xv[i], wp, acc[i][c]);
        }
    }
}

// store to transposed partial layout [j][b]
__device__ __forceinline__ void store_T(float* __restrict__ dst, int n0,
                                        int bpg, int cg, float2 acc[4][4]) {
    #pragma unroll
    for (int c = 0; c < 4; c++) {
        int j3 = n0 + cg * 4 + c;
        #pragma unroll
        for (int i = 0; i < 4; i++) {
            int p = bpg + 8 * i;
            dst[j3 * 64 + 2 * p]     = acc[i][c].x;
            dst[j3 * 64 + 2 * p + 1] = acc[i][c].y;
        }
    }
}

// store to old layout [b][N] (used for r1 partials)
__device__ __forceinline__ void store_BN(float* __restrict__ dst, int N, int n0,
                                         int bpg, int cg, float2 acc[4][4]) {
    #pragma unroll
    for (int c = 0; c < 4; c++) {
        int n = n0 + cg * 4 + c;
        #pragma unroll
        for (int i = 0; i < 4; i++) {
            int p = bpg + 8 * i;
            dst[(size_t)(2 * p) * N + n]     = acc[i][c].x;
            dst[(size_t)(2 * p + 1) * N + n] = acc[i][c].y;
        }
    }
}

// ---------------- generic batch-64 GEMM (proven R3/R4 kernel; used for logits) ----------------
#define KT 64

template<int JT, int NTH>
__launch_bounds__(NTH)
__global__ void gemm64k(const float* __restrict__ XT, const float* __restrict__ W,
                        const float* __restrict__ bias, float* __restrict__ out,
                        int N, int ldW, int K, int kChunk)
{
    __shared__ float xs[KT * 66];
    __shared__ float ws[JT * (KT + 1)];

    const int tid = threadIdx.x;
    const int n0  = blockIdx.x * JT;
    const int kb  = blockIdx.y * kChunk;
    const int ke  = min(K, kb + kChunk);
    const int bpg = tid & 7;
    const int cg  = tid >> 3;

    float2 acc[4][4];
    #pragma unroll
    for (int i = 0; i < 4; i++)
        #pragma unroll
        for (int c = 0; c < 4; c++) acc[i][c] = make_float2(0.f, 0.f);

    for (int kt = kb; kt < ke; kt += KT) {
        const int kn = min(KT, ke - kt);
        __syncthreads();
        for (int e = tid; e < kn * 64; e += NTH) {
            int k = e >> 6, b = e & 63;
            xs[k * 66 + b] = XT[(kt + k) * 64 + b];
        }
        for (int e = tid; e < JT * KT; e += NTH) {
            int nl = e >> 6, k = e & 63;
            int n = n0 + nl;
            ws[nl * (KT + 1) + k] = (n < N && k < kn) ? W[(size_t)n * ldW + kt + k] : 0.f;
        }
        __syncthreads();

        #pragma unroll 4
        for (int k = 0; k < kn; k++) {
            float2 xv[4];
            #pragma unroll
            for (int i = 0; i < 4; i++)
                xv[i] = *reinterpret_cast<const float2*>(&xs[k * 66 + 2 * (bpg + 8 * i)]);
            #pragma unroll
            for (int c = 0; c < 4; c++) {
                float wv = ws[(cg * 4 + c) * (KT + 1) + k];
                float2 wp = make_float2(wv, wv);
                #pragma unroll
                for (int i = 0; i < 4; i++)
                    acc[i][c] = ffma2(xv[i], wp, acc[i][c]);
            }
        }
    }

    float* o = out + (size_t)blockIdx.y * 64 * N;
    #pragma unroll
    for (int c = 0; c < 4; c++) {
        int n = n0 + cg * 4 + c;
        if (n >= N) continue;
        float bv = bias ? bias[n] : 0.f;
        #pragma unroll
        for (int i = 0; i < 4; i++) {
            int p = bpg + 8 * i;
            o[(size_t)(2 * p)     * N + n] = acc[i][c].x + bv;
            o[(size_t)(2 * p + 1) * N + n] = acc[i][c].y + bv;
        }
    }
}

// ---------------- encoder gh GEMM: grid (24, 8), transposed partial store ----------------
__global__ __launch_bounds__(128)
void enc_gemm(const float* __restrict__ h, const float* __restrict__ W_hh)
{
    __shared__ float xs[64 * 66];
    __shared__ float ws[64 * 65];
    const int tid = threadIdx.x;
    const int jn = blockIdx.x, jk = blockIdx.y;
    const int n0 = jn * 64, k0 = jk * 64;
    const int bpg = tid & 7, cg = tid >> 3;

    for (int e = tid; e < 4096; e += 128) {
        int k = e >> 6, b = e & 63;
        xs[k * 66 + b] = h[(k0 + k) * 64 + b];
    }
    for (int e = tid; e < 4096; e += 128) {
        int nl = e >> 6, k = e & 63;
        ws[nl * 65 + k] = W_hh[(size_t)(n0 + nl) * HID + k0 + k];
    }
    __syncthreads();

    float2 acc[4][4];
    #pragma unroll
    for (int i = 0; i < 4; i++)
        #pragma unroll
        for (int c = 0; c < 4; c++) acc[i][c] = make_float2(0.f, 0.f);
    mm64_4x4(xs, ws, bpg, cg, acc);
    store_T(g_A + (size_t)jk * G3 * 64, n0, bpg, cg, acc);
}

// ---------------- decoder gi+gh GEMM with fused input gather: grid (24, 13) ----------------
__global__ __launch_bounds__(128)
void dec_gemm_both(const float* __restrict__ h,
                   const float* __restrict__ emb_dec,
                   const float* __restrict__ W_ih, const float* __restrict__ W_hh)
{
    __shared__ float xs[64 * 66];
    __shared__ float ws[64 * 65];
    const int tid = threadIdx.x;
    const int jn = blockIdx.x, jk = blockIdx.y;
    const int n0 = jn * 64;
    const int bpg = tid & 7, cg = tid >> 3;

    if (jk < 5) {           // input part: emb_dec[idx] ++ rate, K chunk jk*64
        int kb = jk * 64;
        for (int e = tid; e < 4096; e += 128) {
            int b = e >> 6, kl = e & 63, kk = kb + kl;
            float v = 0.f;
            if (kk < EMB)       v = emb_dec[(size_t)g_idx[b] * EMB + kk];
            else if (kk == EMB) v = g_rate[b];
            xs[kl * 66 + b] = v;
        }
        for (int e = tid; e < 4096; e += 128) {
            int nl = e >> 6, k = e & 63, kk = kb + k;
            ws[nl * 65 + k] = (kk < EMB + 1) ? W_ih[(size_t)(n0 + nl) * (EMB + 1) + kk] : 0.f;
        }
    } else {                // hidden part
        int kb = (jk - 5) * 64;
        for (int e = tid; e < 4096; e += 128) {
            int k = e >> 6, b = e & 63;
            xs[k * 66 + b] = h[(kb + k) * 64 + b];
        }
        for (int e = tid; e < 4096; e += 128) {
            int nl = e >> 6, k = e & 63;
            ws[nl * 65 + k] = W_hh[(size_t)(n0 + nl) * HID + kb + k];
        }
    }
    __syncthreads();

    float2 acc[4][4];
    #pragma unroll
    for (int i = 0; i < 4; i++)
        #pragma unroll
        for (int c = 0; c < 4; c++) acc[i][c] = make_float2(0.f, 0.f);
    mm64_4x4(xs, ws, bpg, cg, acc);
    float* dst = (jk < 5) ? (g_Bp + (size_t)jk * G3 * 64) : (g_A + (size_t)(jk - 5) * G3 * 64);
    store_T(dst, n0, bpg, cg, acc);
}

// ---------------- GRU gate combine, fully coalesced [p][j][b] layout ----------------
__global__ void combine_T(const float* __restrict__ Ap, int nA,
                          const float* __restrict__ Bsrc, int nB,
                          const float* __restrict__ b_ih, const float* __restrict__ b_hh,
                          const float* __restrict__ hin, float* __restrict__ hout,
                          const int* __restrict__ src_len, int t)
{
    int i = blockIdx.x * blockDim.x + threadIdx.x;   // 128 x 256 = 32768
    if (i >= B * HID) return;
    const int j = i >> 6, b = i & 63;

    float ar = b_hh[j], az = b_hh[j + 512], an = b_hh[j + 1024];
    #pragma unroll 4
    for (int p = 0; p < nA; p++) {
        const float* a = Ap + (size_t)p * G3 * 64;
        ar += a[j * 64 + b]; az += a[(j + 512) * 64 + b]; an += a[(j + 1024) * 64 + b];
    }
    float br, bz, bn;
    if (nB == 0) {     // Bsrc = gi [j][b], bias included
        br = Bsrc[j * 64 + b]; bz = Bsrc[(j + 512) * 64 + b]; bn = Bsrc[(j + 1024) * 64 + b];
    } else {
        br = b_ih[j]; bz = b_ih[j + 512]; bn = b_ih[j + 1024];
        #pragma unroll 4
        for (int p = 0; p < nB; p++) {
            const float* a = Bsrc + (size_t)p * G3 * 64;
            br += a[j * 64 + b]; bz += a[(j + 512) * 64 + b]; bn += a[(j + 1024) * 64 + b];
        }
    }
    float r = sigf(ar + br);
    float z = sigf(az + bz);
    float n = tanhf(bn + r * an);
    float ho = hin[j * 64 + b];
    float hv = (1.f - z) * n + z * ho;
    if (src_len && !(t < src_len[b])) hv = ho;
    hout[j * 64 + b] = hv;
}

// ---------------- r1 GEMM with fused concat gather: grid (8, 12) ----------------
__global__ __launch_bounds__(128)
void r1_gemm_fused(const float* __restrict__ emb_mt, const float* __restrict__ hT,
                   const float* __restrict__ W_r1, float* __restrict__ C)
{
    __shared__ float xs[64 * 66];
    __shared__ float ws[64 * 65];
    const int tid = threadIdx.x, jn = blockIdx.x, jk = blockIdx.y;
    const int n0 = jn * 64, k0 = jk * 64;
    const int bpg = tid & 7, cg = tid >> 3;

    if (k0 < EMB) {
        for (int e = tid; e < 4096; e += 128) {
            int b = e >> 6, kl = e & 63;
            xs[kl * 66 + b] = emb_mt[(size_t)g_idx[b] * EMB + k0 + kl];
        }
    } else {
        for (int e = tid; e < 4096; e += 128) {
            int k = e >> 6, b = e & 63;
            xs[k * 66 + b] = hT[(k0 - EMB + k) * 64 + b];
        }
    }
    for (int e = tid; e < 4096; e += 128) {
        int nl = e >> 6, k = e & 63;
        ws[nl * 65 + k] = W_r1[(size_t)(n0 + nl) * (EMB + HID) + k0 + k];
    }
    __syncthreads();

    float2 acc[4][4];
    #pragma unroll
    for (int i = 0; i < 4; i++)
        #pragma unroll
        for (int c = 0; c < 4; c++) acc[i][c] = make_float2(0.f, 0.f);
    mm64_4x4(xs, ws, bpg, cg, acc);
    store_BN(C + (size_t)jk * B * HID, HID, n0, bpg, cg, acc);
}

// ---------------- softmax partials: 320 blocks = 64 b x 5 slices of 6000 ----------------
__global__ void softmax_partials(void)
{
    __shared__ float rm[256], rs[256];
    __shared__ int   ri[256];
    const int b = blockIdx.x & 63, sl = blockIdx.x >> 6, tid = threadIdx.x;
    const float* L = g_logits + (size_t)b * EID;
    const int n0 = sl * 6000;

    float m = -3.4e38f, sum = 0.f; int ix = 0x7fffffff;
    for (int n = n0 + tid; n < n0 + 6000; n += 256) {
        float v = L[n];
        if (v > m) { sum = sum * expf(m - v) + 1.f; m = v; ix = n; }
        else       sum += expf(v - m);
    }
    rm[tid] = m; rs[tid] = sum; ri[tid] = ix;
    __syncthreads();
    for (int st = 128; st; st >>= 1) {
        if (tid < st) {
            float m1 = rm[tid], m2 = rm[tid + st], s1 = rs[tid], s2 = rs[tid + st];
            int i1 = ri[tid], i2 = ri[tid + st];
            float M = fmaxf(m1, m2);
            rs[tid] = s1 * expf(m1 - M) + s2 * expf(m2 - M);
            rm[tid] = M;
            ri[tid] = (m2 > m1) ? i2 : ((m1 > m2) ? i1 : min(i1, i2));
        }
        __syncthreads();
    }
    if (tid == 0) {
        g_pm[b * 5 + sl] = rm[0]; g_ps[b * 5 + sl] = rs[0]; g_pi[b * 5 + sl] = ri[0];
    }
}

// merge the 5 per-slice partials of batch b -> (lse, first-argmax)
__device__ __forceinline__ void merge5(int b, float& lse, int& amax) {
    float M = -3.4e38f, S = 0.f; int I = 0x7fffffff;
    #pragma unroll
    for (int sl = 0; sl < 5; sl++) {
        float m2 = g_pm[b * 5 + sl], s2 = g_ps[b * 5 + sl];
        int i2 = g_pi[b * 5 + sl];
        float Mn = fmaxf(M, m2);
        S = S * expf(M - Mn) + s2 * expf(m2 - Mn);
        I = (m2 > M) ? i2 : ((M > m2) ? I : min(I, i2));
        M = Mn;
    }
    lse = M + logf(S);
    amax = I;
}

// ---------------- softmax write + argmax publish: 320 blocks ----------------
__global__ void softmax_write(float* __restrict__ out, int row)
{
    const int b = blockIdx.x & 63, sl = blockIdx.x >> 6, tid = threadIdx.x;
    float lse; int amax; merge5(b, lse, amax);
    const float* L = g_logits + (size_t)b * EID;
    float* O = out + ((size_t)row * B + b) * EID;
    for (int n = sl * 6000 + tid; n < sl * 6000 + 6000; n += 256) O[n] = L[n] - lse;
    if (sl == 0 && tid == 0) g_idx[b] = amax;
}

// ---------------- rate head finish (proven R3 kernel) ----------------
__global__ void rate_head(const float* __restrict__ C, const float* __restrict__ b_r1,
                          const float* __restrict__ W_r2, const float* __restrict__ b_r2,
                          float* __restrict__ outRate, int row, float* __restrict__ rateState)
{
    const int b = blockIdx.x, j = threadIdx.x;   // 512 threads
    float v = b_r1[j];
    #pragma unroll
    for (int p = 0; p < 12; p++) v += C[((size_t)p * B + b) * HID + j];
    v = fmaxf(v, 0.f) * W_r2[j];
    __shared__ float sv[512];
    sv[j] = v; __syncthreads();
    for (int s = 256; s; s >>= 1) { if (j < s) sv[j] += sv[j + s]; __syncthreads(); }
    if (j == 0) {
        float pr = sigf(sv[0] + b_r2[0]);
        outRate[(size_t)row * B + b] = pr;
        rateState[b] = pr;
    }
}

// ---------------- prep kernels ----------------
__global__ void init_state(const int* __restrict__ trg_eid, const float* __restrict__ trg_rate)
{
    int i = blockIdx.x * 256 + threadIdx.x;
    if (i < HID * B) g_hT[i] = 0.f;
    if (i < B) { g_idx[i] = trg_eid[i]; g_rate[i] = trg_rate[i]; }
}

// gi[t][j][b] = b_ih[j] + sum_k src[t][b][k] * W_ih[j][k]
__global__ void enc_gi(const float* __restrict__ src, const float* __restrict__ W_ih,
                       const float* __restrict__ b_ih)
{
    const int j = blockIdx.x * 4 + (threadIdx.x >> 6);
    const int b = threadIdx.x & 63;
    const int t = blockIdx.y;
    const float* x = src + ((size_t)t * 64 + b) * 3;
    float v = b_ih[j] + x[0] * W_ih[j * 3] + x[1] * W_ih[j * 3 + 1] + x[2] * W_ih[j * 3 + 2];
    g_giEnc[((size_t)t * G3 + j) * 64 + b] = v;
}

// ---------------- host launcher ----------------
extern "C" void kernel_launch(void* const* d_in, const int* in_sizes, int n_in,
                              void* d_out, int out_size)
{
    const float* src      = (const float*)d_in[0];
    const int*   src_len  = (const int*)  d_in[1];
    const int*   trg_eid  = (const int*)  d_in[2];
    const float* trg_rate = (const float*)d_in[3];
    const float* W_ih_enc = (const float*)d_in[4];
    const float* W_hh_enc = (const float*)d_in[5];
    const float* b_ih_enc = (const float*)d_in[6];
    const float* b_hh_enc = (const float*)d_in[7];
    const float* emb_dec  = (const float*)d_in[8];
    const float* W_ih_dec = (const float*)d_in[9];
    const float* W_hh_dec = (const float*)d_in[10];
    const float* b_ih_dec = (const float*)d_in[11];
    const float* b_hh_dec = (const float*)d_in[12];
    const float* emb_mt   = (const float*)d_in[13];
    const float* W_eid    = (const float*)d_in[14];
    const float* b_eid    = (const float*)d_in[15];
    const float* W_r1     = (const float*)d_in[16];
    const float* b_r1     = (const float*)d_in[17];
    const float* W_r2     = (const float*)d_in[18];
    const float* b_r2     = (const float*)d_in[19];
    float* out = (float*)d_out;
    float* out_rate = out + (size_t)TRG_T * B * EID;

    float *hT, *giEnc, *A, *Bp, *C, *logits, *rate;
    cudaGetSymbolAddress((void**)&hT,     g_hT);
    cudaGetSymbolAddress((void**)&giEnc,  g_giEnc);
    cudaGetSymbolAddress((void**)&A,      g_A);
    cudaGetSymbolAddress((void**)&Bp,     g_Bp);
    cudaGetSymbolAddress((void**)&C,      g_C);
    cudaGetSymbolAddress((void**)&logits, g_logits);
    cudaGetSymbolAddress((void**)&rate,   g_rate);
    float* hbuf[2] = { hT, hT + HID * B };

    // zero output row 0 (eid + rate)
    cudaMemsetAsync(out, 0, (size_t)B * EID * sizeof(float), 0);
    cudaMemsetAsync(out_rate, 0, B * sizeof(float), 0);

    init_state<<<128, 256>>>(trg_eid, trg_rate);
    enc_gi<<<dim3(384, SRC_T), 256>>>(src, W_ih_enc, b_ih_enc);

    // ---------- encoder: 128 masked GRU steps (2 nodes/step) ----------
    for (int t = 0; t < SRC_T; t++) {
        enc_gemm<<<dim3(24, 8), 128>>>(hbuf[t & 1], W_hh_enc);
        combine_T<<<128, 256>>>(A, 8, giEnc + (size_t)t * G3 * 64, 0,
                                nullptr, b_hh_enc, hbuf[t & 1], hbuf[(t + 1) & 1],
                                src_len, t);
    }

    // ---------- decoder: 49 autoregressive steps (7 nodes/step) ----------
    for (int s = 0; s < TRG_T - 1; s++) {
        const int pi = s & 1, po = (s + 1) & 1;
        dec_gemm_both<<<dim3(24, 13), 128>>>(hbuf[pi], emb_dec, W_ih_dec, W_hh_dec);
        combine_T<<<128, 256>>>(A, 8, Bp, 5, b_ih_dec, b_hh_dec,
                                hbuf[pi], hbuf[po], nullptr, 0);
        // big output projection: proven R3 config
        gemm64k<96, 192><<<dim3(313, 1), 192>>>(hbuf[po], W_eid, b_eid, logits,
                                                EID, HID, HID, HID);
        softmax_partials<<<320, 256>>>();
        softmax_write<<<320, 256>>>(out, s + 1);
        r1_gemm_fused<<<dim3(8, 12), 128>>>(emb_mt, hbuf[po], W_r1, C);
        rate_head<<<64, 512>>>(C, b_r1, W_r2, b_r2, out_rate, s + 1, rate);
    }
}